// round 1
// baseline (speedup 1.0000x reference)
#include <cuda_runtime.h>

#define NPIX   (480*480)
#define NCLS   124
#define FCH    64
#define IN_HW  120
#define EPS_F  1e-8f

// ---------------- device scratch (static, no runtime allocation) ----------------
__device__ float g_feats_t[IN_HW*IN_HW*FCH];   // [y][x][c] channel-contiguous
__device__ float g_mn[NCLS*FCH];               // normalized memory rows
__device__ float g_iszero[NCLS];
__device__ int   g_hist[NCLS];
__device__ int   g_cursor[NCLS];
__device__ int   g_binned[NPIX];               // pix | (cls<<18), sorted by class
__device__ float g_sum[NCLS*FCH];
__device__ float g_wx[NCLS*FCH];
__device__ float g_wsum[NCLS];

// bilinear frac for output phase r (u = o/4 - 0.375, value=(1-f)x[i0]+f x[i0+1])
__constant__ float c_frac[4] = {0.625f, 0.875f, 0.125f, 0.375f};

// ---------------- K0: transpose feats [c][y][x] -> [y][x][c] ----------------
__global__ void k_transpose(const float* __restrict__ feats) {
    __shared__ float tile[FCH*121];             // pad 121: conflict-free on both phases
    const int y = blockIdx.x;                   // 0..119
    for (int i = threadIdx.x; i < FCH*IN_HW; i += blockDim.x) {
        int c = i / IN_HW, x = i - c*IN_HW;     // x fastest -> coalesced global read
        tile[c*121 + x] = feats[c*IN_HW*IN_HW + y*IN_HW + x];
    }
    __syncthreads();
    for (int i = threadIdx.x; i < IN_HW*FCH; i += blockDim.x) {
        int x = i >> 6, c = i & 63;             // c fastest -> coalesced global write
        g_feats_t[(y*IN_HW + x)*FCH + c] = tile[c*121 + x];
    }
}

// ---------------- K1: normalize memory rows, zero accumulators ----------------
__global__ void k_setup(const float* __restrict__ memory) {
    const int c = blockIdx.x;        // class
    const int t = threadIdx.x;       // channel (64 threads)
    float v = memory[c*FCH + t];
    float s = v * v;
    #pragma unroll
    for (int o = 16; o; o >>= 1) s += __shfl_xor_sync(0xffffffffu, s, o);
    __shared__ float sh[2];
    if ((t & 31) == 0) sh[t >> 5] = s;
    __syncthreads();
    float nsq = sh[0] + sh[1];
    float inv = 1.0f / fmaxf(sqrtf(nsq), EPS_F);
    g_mn[c*FCH + t] = v * inv;       // zero rows stay exactly zero
    g_sum[c*FCH + t] = 0.0f;
    g_wx [c*FCH + t] = 0.0f;
    if (t == 0) {
        g_iszero[c] = (nsq == 0.0f) ? 1.0f : 0.0f;
        g_wsum[c] = 0.0f;
        g_hist[c] = 0;
        g_cursor[c] = 0;
    }
}

// ---------------- K2: class histogram ----------------
__global__ void k_hist(const int* __restrict__ seg) {
    __shared__ int h[NCLS];
    for (int i = threadIdx.x; i < NCLS; i += blockDim.x) h[i] = 0;
    __syncthreads();
    for (int i = blockIdx.x*blockDim.x + threadIdx.x; i < NPIX; i += gridDim.x*blockDim.x)
        atomicAdd(&h[seg[i]], 1);
    __syncthreads();
    for (int i = threadIdx.x; i < NCLS; i += blockDim.x)
        if (h[i]) atomicAdd(&g_hist[i], h[i]);
}

// ---------------- K3: exclusive scan -> bin cursors ----------------
__global__ void k_scan() {
    __shared__ int sh[128];
    const int t = threadIdx.x;
    int h = (t < NCLS) ? g_hist[t] : 0;
    sh[t] = h;
    __syncthreads();
    #pragma unroll
    for (int o = 1; o < 128; o <<= 1) {
        int u = (t >= o) ? sh[t - o] : 0;
        __syncthreads();
        sh[t] += u;
        __syncthreads();
    }
    if (t < NCLS) g_cursor[t] = sh[t] - h;     // exclusive prefix
}

// ---------------- K4: scatter pixel ids into class-sorted order ----------------
__global__ void k_bin(const int* __restrict__ seg) {
    int i = blockIdx.x*blockDim.x + threadIdx.x;
    if (i < NPIX) {
        int c = seg[i];
        int slot = atomicAdd(&g_cursor[c], 1);
        g_binned[slot] = i | (c << 18);        // pix < 2^18, cls < 2^7
    }
}

// ---------------- K6: main — bilinear + similarity weight + class sums ----------------
// Warp-per-pixel, lane handles channels (2*lane, 2*lane+1). Binned order ->
// same-class runs -> register accumulation, atomic flush only at class changes.
__global__ void __launch_bounds__(256) k_main() {
    const int lane = threadIdx.x & 31;
    const int gw   = (blockIdx.x*blockDim.x + threadIdx.x) >> 5;
    const int nw   = (gridDim.x*blockDim.x) >> 5;
    const int chunk = (NPIX + nw - 1) / nw;
    int j = gw * chunk;
    const int jend = min(j + chunk, NPIX);
    if (j >= jend) return;

    const float2* __restrict__ ft  = (const float2*)g_feats_t;
    const float2* __restrict__ mn2 = (const float2*)g_mn;

    float s0=0.f, s1=0.f, w0=0.f, w1=0.f, aw=0.f;
    float m0=0.f, m1=0.f;
    int cur = -1;

    for (; j < jend; ++j) {
        const int packed = g_binned[j];        // warp-uniform broadcast load
        const int cls = packed >> 18;
        const int pix = packed & 0x3FFFF;

        if (cls != cur) {                      // warp-uniform branch
            if (cur >= 0) {
                atomicAdd(&g_sum[cur*FCH + 2*lane],     s0);
                atomicAdd(&g_sum[cur*FCH + 2*lane + 1], s1);
                atomicAdd(&g_wx [cur*FCH + 2*lane],     w0);
                atomicAdd(&g_wx [cur*FCH + 2*lane + 1], w1);
                if (lane == 0) atomicAdd(&g_wsum[cur], aw);
            }
            s0 = s1 = w0 = w1 = aw = 0.f;
            cur = cls;
            float2 m = mn2[cls*32 + lane];
            m0 = m.x; m1 = m.y;
        }

        const int oy = pix / 480;
        const int ox = pix - oy*480;
        const int iy0 = (oy >> 2) + ((oy & 3) >> 1) - 1;
        const int ix0 = (ox >> 2) + ((ox & 3) >> 1) - 1;
        const float fy = c_frac[oy & 3];
        const float fx = c_frac[ox & 3];
        const int y0 = max(iy0, 0),     y1 = min(iy0 + 1, IN_HW - 1);
        const int x0 = max(ix0, 0),     x1 = min(ix0 + 1, IN_HW - 1);

        float2 a = ft[(y0*IN_HW + x0)*32 + lane];
        float2 b = ft[(y0*IN_HW + x1)*32 + lane];
        float2 c = ft[(y1*IN_HW + x0)*32 + lane];
        float2 d = ft[(y1*IN_HW + x1)*32 + lane];

        float t0 = fmaf(fx, b.x - a.x, a.x);
        float t1 = fmaf(fx, b.y - a.y, a.y);
        float u0 = fmaf(fx, d.x - c.x, c.x);
        float u1 = fmaf(fx, d.y - c.y, c.y);
        float v0 = fmaf(fy, u0 - t0, t0);
        float v1 = fmaf(fy, u1 - t1, t1);

        float nsq = v0*v0 + v1*v1;
        float dt  = v0*m0 + v1*m1;
        #pragma unroll
        for (int o = 16; o; o >>= 1) {
            nsq += __shfl_xor_sync(0xffffffffu, nsq, o);
            dt  += __shfl_xor_sync(0xffffffffu, dt,  o);
        }
        const float w = 1.0f - dt / fmaxf(sqrtf(nsq), EPS_F);

        s0 += v0;              s1 += v1;
        w0 = fmaf(w, v0, w0);  w1 = fmaf(w, v1, w1);
        aw += w;
    }
    if (cur >= 0) {
        atomicAdd(&g_sum[cur*FCH + 2*lane],     s0);
        atomicAdd(&g_sum[cur*FCH + 2*lane + 1], s1);
        atomicAdd(&g_wx [cur*FCH + 2*lane],     w0);
        atomicAdd(&g_wx [cur*FCH + 2*lane + 1], w1);
        if (lane == 0) atomicAdd(&g_wsum[cur], aw);
    }
}

// ---------------- K7: finalize ----------------
__global__ void k_final(const float* __restrict__ memory, float* __restrict__ out) {
    const int c = blockIdx.x;
    const int t = threadIdx.x;
    const int cnt = g_hist[c];
    const float memv = memory[c*FCH + t];
    float res = memv;                           // absent class: keep memory
    if (cnt > 0) {
        if (g_iszero[c] != 0.0f) {
            res = g_sum[c*FCH + t] / fmaxf((float)cnt, 1.0f);   // mean_c
        } else {
            const float ws = g_wsum[c];
            const float weighted = g_wx[c*FCH + t] / ((ws != 0.0f) ? ws : 1.0f);
            res = 0.9f * memv + 0.1f * weighted;                 // momentum update
        }
    }
    out[c*FCH + t] = res;
}

// ---------------- launch ----------------
extern "C" void kernel_launch(void* const* d_in, const int* in_sizes, int n_in,
                              void* d_out, int out_size) {
    const float* feats  = (const float*)d_in[0];   // 1x64x120x120
    const float* memory = (const float*)d_in[1];   // 124x1x64
    const int*   seg    = (const int*)  d_in[2];   // 1x480x480
    float* out = (float*)d_out;                    // 124x1x64

    k_transpose<<<IN_HW, 256>>>(feats);
    k_setup<<<NCLS, FCH>>>(memory);
    k_hist<<<240, 256>>>(seg);
    k_scan<<<1, 128>>>();
    k_bin<<<NPIX/256, 256>>>(seg);                 // 230400 = 900*256 exactly
    k_main<<<296, 256>>>();
    k_final<<<NCLS, FCH>>>(memory, out);
}

// round 3
// speedup vs baseline: 1.6125x; 1.6125x over previous
#include <cuda_runtime.h>

#define NPIX   (480*480)
#define NCLS   124
#define FCH    64
#define IN_HW  120
#define EPS_F  1e-8f

// ---------------- device scratch (zero-initialized at module load; k_final
// restores g_hist to zero after each execution so every graph replay starts
// from a clean state) ----------------
__device__ __align__(16) float g_feats_t[IN_HW*IN_HW*FCH];   // [y][x][c]
__device__ __align__(16) float g_mn[NCLS*FCH];               // normalized memory rows
__device__ float g_iszero[NCLS];
__device__ int   g_hist[NCLS];                               // must be 0 at k_pre entry
__device__ int   g_cursor[NCLS];
__device__ int   g_binned[NPIX];                             // pix | (cls<<18)
__device__ __align__(16) float g_sum[NCLS*FCH];
__device__ __align__(16) float g_wx[NCLS*FCH];
__device__ float g_wsum[NCLS];

__constant__ float c_frac[4] = {0.625f, 0.875f, 0.125f, 0.375f};

// ---------------- K_A: fused transpose + setup + histogram ----------------
// blocks [0,120): transpose row y=b   [120,244): setup class b-120   [244,484): hist
// NOTE: g_hist is NOT zeroed here (it is zero at entry: static init on first
// run, restored by k_final on every run). This removes the setup<->hist race.
__global__ void __launch_bounds__(256) k_pre(const float* __restrict__ feats,
                                             const float* __restrict__ memory,
                                             const int* __restrict__ seg) {
    const int b = blockIdx.x;
    if (b < 120) {
        __shared__ float tile[FCH*121];
        const int y = b;
        for (int i = threadIdx.x; i < FCH*IN_HW; i += 256) {
            int c = i / IN_HW, x = i - c*IN_HW;
            tile[c*121 + x] = feats[c*IN_HW*IN_HW + y*IN_HW + x];
        }
        __syncthreads();
        for (int i = threadIdx.x; i < IN_HW*FCH; i += 256) {
            int x = i >> 6, c = i & 63;
            g_feats_t[(y*IN_HW + x)*FCH + c] = tile[c*121 + x];
        }
    } else if (b < 244) {
        const int c = b - 120;
        const int t = threadIdx.x;
        // warp 0 only: lane t owns channels t and t+32. No shared mem, no sync.
        if (t < 32) {
            float v0 = memory[c*FCH + t];
            float v1 = memory[c*FCH + t + 32];
            float s = v0*v0 + v1*v1;
            #pragma unroll
            for (int o = 16; o; o >>= 1) s += __shfl_xor_sync(0xffffffffu, s, o);
            float inv = 1.0f / fmaxf(sqrtf(s), EPS_F);
            g_mn[c*FCH + t]      = v0 * inv;
            g_mn[c*FCH + t + 32] = v1 * inv;
            if (t == 0) {
                g_iszero[c] = (s == 0.0f) ? 1.0f : 0.0f;
                g_wsum[c] = 0.0f;
            }
        } else if (t < 96) {                 // disjoint threads zero accumulators
            g_sum[c*FCH + (t - 32)] = 0.0f;
            g_wx [c*FCH + (t - 32)] = 0.0f;
        }
    } else {
        __shared__ int h[NCLS];
        for (int i = threadIdx.x; i < NCLS; i += 256) h[i] = 0;
        __syncthreads();
        const int nb = gridDim.x - 244;
        for (int i = (b-244)*256 + threadIdx.x; i < NPIX; i += nb*256)
            atomicAdd(&h[seg[i]], 1);
        __syncthreads();
        for (int i = threadIdx.x; i < NCLS; i += 256)
            if (h[i]) atomicAdd(&g_hist[i], h[i]);
    }
}

// ---------------- K_B: exclusive scan -> cursors ----------------
__global__ void k_scan() {
    __shared__ int sh[128];
    const int t = threadIdx.x;
    int h = (t < NCLS) ? g_hist[t] : 0;
    sh[t] = h;
    __syncthreads();
    #pragma unroll
    for (int o = 1; o < 128; o <<= 1) {
        int u = (t >= o) ? sh[t - o] : 0;
        __syncthreads();
        sh[t] += u;
        __syncthreads();
    }
    if (t < NCLS) g_cursor[t] = sh[t] - h;
}

// ---------------- K_C: scatter into class-sorted order ----------------
__global__ void k_bin(const int* __restrict__ seg) {
    int i = blockIdx.x*blockDim.x + threadIdx.x;
    if (i < NPIX) {
        int c = seg[i];
        int slot = atomicAdd(&g_cursor[c], 1);
        g_binned[slot] = i | (c << 18);
    }
}

// ---------------- K_D: main ----------------
// 8 lanes per pixel (subgroup), 4 pixels per warp iteration.
// lane sl covers channels {4sl..4sl+3} and {32+4sl..32+4sl+3} (two coalesced
// 128B-line LDG.128 per tap). Register accumulation per subgroup, float4 REDG
// flush on class change / exit.
__global__ void __launch_bounds__(256) k_main() {
    const int lane = threadIdx.x & 31;
    const int sub  = lane >> 3;
    const int sl   = lane & 7;
    const int gw   = (blockIdx.x*blockDim.x + threadIdx.x) >> 5;
    const int nw   = (gridDim.x*blockDim.x) >> 5;
    const int chunk = (NPIX + nw - 1) / nw;
    const int j0   = gw * chunk;
    const int jend = min(j0 + chunk, NPIX);
    if (j0 >= jend) return;

    const float4* __restrict__ ft4 = (const float4*)g_feats_t;  // row = 16 float4
    const float4* __restrict__ mn4 = (const float4*)g_mn;

    float4 sA = {0,0,0,0}, sB = {0,0,0,0}, wA = {0,0,0,0}, wB = {0,0,0,0};
    float  aw = 0.f;
    float4 mA = {0,0,0,0}, mB = {0,0,0,0};
    int cur = -1;

    for (int j = j0; j < jend; j += 4) {
        const int idx    = j + sub;
        const bool valid = idx < jend;
        const int packed = g_binned[valid ? idx : (jend - 1)];
        const int cls = packed >> 18;
        const int pix = packed & 0x3FFFF;

        // tap geometry
        const int oy = pix / 480;
        const int ox = pix - oy*480;
        const int iy0 = (oy >> 2) + ((oy >> 1) & 1) - 1;
        const int ix0 = (ox >> 2) + ((ox >> 1) & 1) - 1;
        const float fy = c_frac[oy & 3];
        const float fx = c_frac[ox & 3];
        const int y0 = max(iy0, 0), y1 = min(iy0 + 1, IN_HW - 1);
        const int x0 = max(ix0, 0), x1 = min(ix0 + 1, IN_HW - 1);
        const float w11 = fy * fx;
        const float w10 = fy - w11;
        const float w01 = fx - w11;
        const float w00 = 1.0f - fy - fx + w11;

        const int rA = (y0*IN_HW + x0)*16, rB = (y0*IN_HW + x1)*16;
        const int rC = (y1*IN_HW + x0)*16, rD = (y1*IN_HW + x1)*16;
        // issue all 8 tap loads up front (independent, coalesced per subgroup)
        const float4 a0 = ft4[rA + sl],     b0 = ft4[rB + sl];
        const float4 c0 = ft4[rC + sl],     d0 = ft4[rD + sl];
        const float4 a1 = ft4[rA + 8 + sl], b1 = ft4[rB + 8 + sl];
        const float4 c1 = ft4[rC + 8 + sl], d1 = ft4[rD + 8 + sl];

        // class-change flush (warp-rare; uniform within each subgroup)
        if (__any_sync(0xffffffffu, cls != cur)) {
            if (cls != cur) {
                if (cur >= 0) {
                    atomicAdd((float4*)&g_sum[cur*FCH + 4*sl],      sA);
                    atomicAdd((float4*)&g_sum[cur*FCH + 32 + 4*sl], sB);
                    atomicAdd((float4*)&g_wx [cur*FCH + 4*sl],      wA);
                    atomicAdd((float4*)&g_wx [cur*FCH + 32 + 4*sl], wB);
                    if (sl == 0) atomicAdd(&g_wsum[cur], aw);
                }
                sA = make_float4(0,0,0,0); sB = make_float4(0,0,0,0);
                wA = make_float4(0,0,0,0); wB = make_float4(0,0,0,0);
                aw = 0.f;
                cur = cls;
                mA = mn4[cls*16 + sl];
                mB = mn4[cls*16 + 8 + sl];
            }
        }

        // bilinear interp of 8 channels
        float4 v0, v1;
        v0.x = w00*a0.x + w01*b0.x + w10*c0.x + w11*d0.x;
        v0.y = w00*a0.y + w01*b0.y + w10*c0.y + w11*d0.y;
        v0.z = w00*a0.z + w01*b0.z + w10*c0.z + w11*d0.z;
        v0.w = w00*a0.w + w01*b0.w + w10*c0.w + w11*d0.w;
        v1.x = w00*a1.x + w01*b1.x + w10*c1.x + w11*d1.x;
        v1.y = w00*a1.y + w01*b1.y + w10*c1.y + w11*d1.y;
        v1.z = w00*a1.z + w01*b1.z + w10*c1.z + w11*d1.z;
        v1.w = w00*a1.w + w01*b1.w + w10*c1.w + w11*d1.w;

        float nsq = v0.x*v0.x + v0.y*v0.y + v0.z*v0.z + v0.w*v0.w
                  + v1.x*v1.x + v1.y*v1.y + v1.z*v1.z + v1.w*v1.w;
        float dt  = v0.x*mA.x + v0.y*mA.y + v0.z*mA.z + v0.w*mA.w
                  + v1.x*mB.x + v1.y*mB.y + v1.z*mB.z + v1.w*mB.w;
        #pragma unroll
        for (int o = 4; o; o >>= 1) {          // reduce within 8-lane subgroup
            nsq += __shfl_xor_sync(0xffffffffu, nsq, o);
            dt  += __shfl_xor_sync(0xffffffffu, dt,  o);
        }
        const float wgt = 1.0f - dt * rsqrtf(fmaxf(nsq, 1e-16f));
        const float vv = valid ? 1.0f : 0.0f;
        const float g  = valid ? wgt : 0.0f;

        sA.x = fmaf(vv, v0.x, sA.x); sA.y = fmaf(vv, v0.y, sA.y);
        sA.z = fmaf(vv, v0.z, sA.z); sA.w = fmaf(vv, v0.w, sA.w);
        sB.x = fmaf(vv, v1.x, sB.x); sB.y = fmaf(vv, v1.y, sB.y);
        sB.z = fmaf(vv, v1.z, sB.z); sB.w = fmaf(vv, v1.w, sB.w);
        wA.x = fmaf(g, v0.x, wA.x);  wA.y = fmaf(g, v0.y, wA.y);
        wA.z = fmaf(g, v0.z, wA.z);  wA.w = fmaf(g, v0.w, wA.w);
        wB.x = fmaf(g, v1.x, wB.x);  wB.y = fmaf(g, v1.y, wB.y);
        wB.z = fmaf(g, v1.z, wB.z);  wB.w = fmaf(g, v1.w, wB.w);
        aw += g;
    }

    if (cur >= 0) {
        atomicAdd((float4*)&g_sum[cur*FCH + 4*sl],      sA);
        atomicAdd((float4*)&g_sum[cur*FCH + 32 + 4*sl], sB);
        atomicAdd((float4*)&g_wx [cur*FCH + 4*sl],      wA);
        atomicAdd((float4*)&g_wx [cur*FCH + 32 + 4*sl], wB);
        if (sl == 0) atomicAdd(&g_wsum[cur], aw);
    }
}

// ---------------- K_E: finalize + restore g_hist to zero for next replay ----
__global__ void k_final(const float* __restrict__ memory, float* __restrict__ out) {
    const int c = blockIdx.x;
    const int t = threadIdx.x;
    const int cnt = g_hist[c];
    const float memv = memory[c*FCH + t];
    float res = memv;
    if (cnt > 0) {
        if (g_iszero[c] != 0.0f) {
            res = g_sum[c*FCH + t] / fmaxf((float)cnt, 1.0f);
        } else {
            const float ws = g_wsum[c];
            const float weighted = g_wx[c*FCH + t] / ((ws != 0.0f) ? ws : 1.0f);
            res = 0.9f * memv + 0.1f * weighted;
        }
    }
    out[c*FCH + t] = res;
    __syncthreads();                 // everyone has read g_hist[c]
    if (t == 0) g_hist[c] = 0;       // clean state for the next execution
}

// ---------------- launch ----------------
extern "C" void kernel_launch(void* const* d_in, const int* in_sizes, int n_in,
                              void* d_out, int out_size) {
    const float* feats  = (const float*)d_in[0];
    const float* memory = (const float*)d_in[1];
    const int*   seg    = (const int*)  d_in[2];
    float* out = (float*)d_out;

    k_pre<<<484, 256>>>(feats, memory, seg);
    k_scan<<<1, 128>>>();
    k_bin<<<NPIX/256, 256>>>(seg);
    k_main<<<296, 256>>>();
    k_final<<<NCLS, FCH>>>(memory, out);
}